// round 10
// baseline (speedup 1.0000x reference)
#include <cuda_runtime.h>
#include <cuda_fp16.h>
#include <math.h>
#include <stdint.h>

#define B_ 8
#define T_ 4096
#define D_ 768
#define DI_ 1536
#define M_ (B_*T_)          // 32768 rows
#define CB_ 256             // chunk
#define NSTEP_ (T_/CB_)     // 16
#define DD_ ((size_t)D_*D_)
#define SROW_ 40            // fp16 SMEM row stride (halfs)
#define NKST_ 3             // cp.async stages
#define STAGE_HALFS_ (128*SROW_)
#define GSM_ (2*NKST_*STAGE_HALFS_*2)   // 61440 bytes dynamic SMEM

// ---------------- scratch ---------------------------------------------------
__device__ float  g_out[(size_t)M_*D_];
__device__ __half g_xnh[(size_t)M_*D_];
__device__ __half g_valh[(size_t)M_*DI_];
__device__ __half g_gateh[(size_t)M_*DI_];
__device__ __half g_hh[(size_t)M_*DI_];
__device__ __half g_outh[(size_t)M_*D_];
__device__ __half g_vh[(size_t)M_*D_];
__device__ __half g_vT[(size_t)M_*D_];     // [b][d][t]
__device__ __half g_vTs[(size_t)M_*D_];    // [b][d][t] * gamma^(CB-1-(t%CB))
__device__ __half g_koutT[(size_t)M_*D_];  // [b][e][t] = out[t-1][e]
__device__ __half g_Ph[(size_t)B_*NSTEP_*CB_*CB_];
__device__ __half g_U[(size_t)NSTEP_*B_*D_*D_];    // per-chunk updates
__device__ __half g_Whs[(size_t)NSTEP_*B_*D_*D_];  // W prefix snapshots
__device__ __half g_readsh[(size_t)M_*D_];
__device__ __half g_wh[4718592];           // fp16 weight copies
__device__ float g_consts[2];              // [0]=log(gamma), [1]=alpha

// ---------------- asm helpers ------------------------------------------------
#define CP_ASYNC16(dst, src) \
    asm volatile("cp.async.ca.shared.global [%0], [%1], 16;" :: "r"(dst), "l"(src))
#define CP_ASYNC16Z(dst, src, sz) \
    asm volatile("cp.async.ca.shared.global [%0], [%1], 16, %2;" :: "r"(dst), "l"(src), "r"(sz))
#define CP_COMMIT()  asm volatile("cp.async.commit_group;" ::: "memory")
#define CP_WAIT1()   asm volatile("cp.async.wait_group 1;" ::: "memory")

#define LDSM4(r, addr) \
    asm volatile("ldmatrix.sync.aligned.m8n8.x4.shared.b16 {%0,%1,%2,%3}, [%4];" \
        : "=r"((r)[0]), "=r"((r)[1]), "=r"((r)[2]), "=r"((r)[3]) : "r"(addr))

__device__ __forceinline__ void mma_h(float* c, const uint32_t* a, const uint32_t* b) {
    asm volatile(
        "mma.sync.aligned.m16n8k16.row.col.f32.f16.f16.f32 "
        "{%0,%1,%2,%3}, {%4,%5,%6,%7}, {%8,%9}, {%0,%1,%2,%3};"
        : "+f"(c[0]), "+f"(c[1]), "+f"(c[2]), "+f"(c[3])
        : "r"(a[0]), "r"(a[1]), "r"(a[2]), "r"(a[3]), "r"(b[0]), "r"(b[1]));
}

// ---------------- shared pipelined fp16 mainloop (64x64 warp tiles) ---------
// 128 threads, 4 warps as 2(m) x 2(n), warp tile 64x64, BK=32 per stage.
// Ag/Bg pre-offset per-thread to row (tile0+tid); k advances 32/stage.
__device__ __forceinline__ void hloop(
    const __half* __restrict__ Ag, const __half* __restrict__ Bg,
    int nk, int bsz, __half* As, __half* Bs, float acc[4][8][4],
    int warp_m, int warp_n, int lane, int tid)
{
    uint32_t aBase = (uint32_t)__cvta_generic_to_shared(As);
    uint32_t bBase = (uint32_t)__cvta_generic_to_shared(Bs);
    uint32_t dA = aBase + (tid * SROW_) * 2;
    uint32_t dB = bBase + (tid * SROW_) * 2;

    auto ISSUE = [&](int s) {
        uint32_t offs = (uint32_t)(s % NKST_) * (STAGE_HALFS_ * 2);
        const __half* ag = Ag + s * 32;
        const __half* bg = Bg + s * 32;
        CP_ASYNC16(dA + offs,      ag);
        CP_ASYNC16(dA + offs + 16, ag + 8);
        CP_ASYNC16(dA + offs + 32, ag + 16);
        CP_ASYNC16(dA + offs + 48, ag + 24);
        CP_ASYNC16Z(dB + offs,      bg,      bsz);
        CP_ASYNC16Z(dB + offs + 16, bg + 8,  bsz);
        CP_ASYNC16Z(dB + offs + 32, bg + 16, bsz);
        CP_ASYNC16Z(dB + offs + 48, bg + 24, bsz);
    };

    ISSUE(0); CP_COMMIT();
    if (nk > 1) ISSUE(1);
    CP_COMMIT();

    int lr = lane & 15, lk = (lane >> 4) << 3;
    for (int s = 0; s < nk; s++) {
        CP_WAIT1();
        __syncthreads();
        if (s + 2 < nk) ISSUE(s + 2);
        CP_COMMIT();

        uint32_t st = (uint32_t)(s % NKST_) * (STAGE_HALFS_ * 2);
        uint32_t aS = aBase + st, bS = bBase + st;
        #pragma unroll
        for (int ks = 0; ks < 32; ks += 16) {
            uint32_t af[4][4];
            #pragma unroll
            for (int mt = 0; mt < 4; mt++)
                LDSM4(af[mt], aS + ((warp_m * 64 + mt * 16 + lr) * SROW_ + ks + lk) * 2);
            #pragma unroll
            for (int p = 0; p < 4; p++) {
                uint32_t bf[4];
                LDSM4(bf, bS + ((warp_n * 64 + p * 16 + lr) * SROW_ + ks + lk) * 2);
                uint32_t be[2] = { bf[0], bf[2] };
                uint32_t bo[2] = { bf[1], bf[3] };
                #pragma unroll
                for (int mt = 0; mt < 4; mt++) {
                    mma_h(acc[mt][2*p],   af[mt], be);
                    mma_h(acc[mt][2*p+1], af[mt], bo);
                }
            }
        }
    }
    __syncthreads();   // protect SMEM for any subsequent phase
}

// ---------------- small kernels ---------------------------------------------
__global__ void k_consts(const float* __restrict__ decay,
                         const float* __restrict__ log_alpha) {
    float g = 1.f / (1.f + expf(-decay[0]));
    g_consts[0] = logf(g);
    g_consts[1] = expf(log_alpha[0]);
}

__global__ void k_h2(const float* __restrict__ src, __half* __restrict__ dst, int n2) {
    int i = blockIdx.x * 256 + threadIdx.x;
    if (i < n2) {
        float2 v = *(const float2*)(src + i * 2);
        *(__half2*)(dst + i * 2) = __floats2half2_rn(v.x, v.y);
    }
}

__global__ void k_xnorm(const float* __restrict__ x, const float* __restrict__ nw) {
    int warp = threadIdx.x >> 5, lane = threadIdx.x & 31;
    int row = blockIdx.x * 8 + warp;
    const float* p = x + (size_t)row * D_;
    float s = 0.f;
    #pragma unroll
    for (int i = lane; i < D_; i += 32) { float v = p[i]; s += v * v; }
    #pragma unroll
    for (int o = 16; o; o >>= 1) s += __shfl_xor_sync(0xffffffffu, s, o);
    float inv = rsqrtf(s * (1.f / D_) + 1e-5f);
    __half* q = g_xnh + (size_t)row * D_;
    #pragma unroll
    for (int i = lane; i < D_; i += 32) q[i] = __float2half(p[i] * inv * nw[i]);
}

// fp16 in/out conv: h = silu(conv(val)+b) * gate
__global__ void k_conv(const float* __restrict__ cw, const float* __restrict__ cb) {
    int e = blockIdx.x * 256 + threadIdx.x;
    int t0 = blockIdx.y * 8;
    int b = blockIdx.z;
    size_t base = ((size_t)b * T_ + t0) * DI_ + e;
    float w0 = cw[e*4+0], w1 = cw[e*4+1], w2 = cw[e*4+2], w3 = cw[e*4+3];
    float bias = cb[e];
    float h0 = (t0 >= 3) ? __half2float(g_valh[base - 3*(size_t)DI_]) : 0.f;
    float h1 = (t0 >= 2) ? __half2float(g_valh[base - 2*(size_t)DI_]) : 0.f;
    float h2 = (t0 >= 1) ? __half2float(g_valh[base - 1*(size_t)DI_]) : 0.f;
    #pragma unroll
    for (int j = 0; j < 8; j++) {
        size_t idx = base + (size_t)j * DI_;
        float cur = __half2float(g_valh[idx]);
        float v = bias + w0*h0 + w1*h1 + w2*h2 + w3*cur;
        h0 = h1; h1 = h2; h2 = cur;
        float s = v / (1.f + __expf(-v));
        g_hh[idx] = __float2half(s * __half2float(g_gateh[idx]));
    }
}

// 32x32 tile transposes -------------------------------------------------------
__global__ void k_transV() {
    __shared__ __half sm[32][33];
    int b = blockIdx.z;
    int t0 = blockIdx.x * 32, d0 = blockIdx.y * 32;
    int tx = threadIdx.x & 31, ty = threadIdx.x >> 5;
    #pragma unroll
    for (int j = 0; j < 4; j++)
        sm[ty + j*8][tx] = g_vh[((size_t)b*T_ + t0 + ty + j*8)*D_ + d0 + tx];
    __syncthreads();
    float gw = __expf((float)(CB_ - 1 - ((t0 + tx) % CB_)) * g_consts[0]);
    #pragma unroll
    for (int j = 0; j < 4; j++) {
        size_t o = ((size_t)b*D_ + d0 + ty + j*8)*T_ + t0 + tx;
        __half v = sm[tx][ty + j*8];
        g_vT[o] = v;
        g_vTs[o] = __float2half(__half2float(v) * gw);
    }
}

__global__ void k_transK() {
    __shared__ __half sm[32][33];
    int b = blockIdx.z;
    int t0 = blockIdx.x * 32, d0 = blockIdx.y * 32;
    int tx = threadIdx.x & 31, ty = threadIdx.x >> 5;
    #pragma unroll
    for (int j = 0; j < 4; j++) {
        int t = t0 + ty + j*8;
        sm[ty + j*8][tx] = (t > 0)
            ? g_outh[((size_t)b*T_ + t - 1)*D_ + d0 + tx] : __float2half(0.f);
    }
    __syncthreads();
    #pragma unroll
    for (int j = 0; j < 4; j++)
        g_koutT[((size_t)b*D_ + d0 + ty + j*8)*T_ + t0 + tx] = sm[tx][ty + j*8];
}

// ---------------- dense fp16 TN GEMM (128 threads, 64x64 warp tiles) --------
// mode 0: acc ; 1: silu ; 2: add1+add2+alpha*acc. C (fp32) / Ch (fp16) optional.
__global__ __launch_bounds__(128, 2) void k_hgemm16(
    const __half* __restrict__ A, const __half* __restrict__ Bm,
    float* __restrict__ C, __half* __restrict__ Ch, int N, int K,
    int mode, const float* __restrict__ add1, const float* __restrict__ add2)
{
    extern __shared__ __align__(16) __half sm16[];
    __half* As = sm16;
    __half* Bs = sm16 + NKST_ * STAGE_HALFS_;
    int tid = threadIdx.x;
    int m0 = blockIdx.y * 128, n0 = blockIdx.x * 128;
    int warp = tid >> 5, lane = tid & 31;
    int warp_m = warp >> 1, warp_n = warp & 1;
    int g = lane >> 2, tq = lane & 3;
    float acc[4][8][4] = {};

    hloop(A + (size_t)(m0 + tid) * K,
          Bm + (size_t)(n0 + tid) * K,
          K >> 5, 16, As, Bs, acc, warp_m, warp_n, lane, tid);

    float alpha = (mode == 2) ? g_consts[1] : 0.f;
    #pragma unroll
    for (int mt = 0; mt < 4; mt++)
        #pragma unroll
        for (int h = 0; h < 2; h++) {
            int mi = m0 + warp_m * 64 + mt * 16 + g + h * 8;
            size_t row = (size_t)mi * N;
            #pragma unroll
            for (int nt = 0; nt < 8; nt++) {
                int ni = n0 + warp_n * 64 + nt * 8 + tq * 2;
                float c0 = acc[mt][nt][h*2 + 0];
                float c1 = acc[mt][nt][h*2 + 1];
                if (mode == 1) {
                    c0 = c0 / (1.f + __expf(-c0));
                    c1 = c1 / (1.f + __expf(-c1));
                } else if (mode == 2) {
                    float2 a1 = *(const float2*)(add1 + row + ni);
                    float2 a2 = *(const float2*)(add2 + row + ni);
                    c0 = a1.x + a2.x + alpha * c0;
                    c1 = a1.y + a2.y + alpha * c1;
                }
                if (C)  *(float2*)(C + row + ni) = make_float2(c0, c1);
                if (Ch) *(__half2*)(Ch + row + ni) = __floats2half2_rn(c0, c1);
            }
        }
}

// ---------------- batched pchunk: P = mask(r@k^T) -> fp16 -------------------
__global__ __launch_bounds__(128, 2) void k_pchunk() {
    extern __shared__ __align__(16) __half sm16[];
    __half* As = sm16;
    __half* Bs = sm16 + NKST_ * STAGE_HALFS_;
    __shared__ float gpow[256];
    int zb = blockIdx.z; int s = zb >> 3; int b = zb & 7;
    int t0 = s * CB_;
    int tid = threadIdx.x;
    int m0 = blockIdx.y * 128, n0 = blockIdx.x * 128;
    int warp = tid >> 5, lane = tid & 31;
    int warp_m = warp >> 1, warp_n = warp & 1;
    int g = lane >> 2, tq = lane & 3;
    float acc[4][8][4] = {};
    float lg = g_consts[0];
    gpow[tid] = __expf((float)tid * lg);
    gpow[tid + 128] = __expf((float)(tid + 128) * lg);

    int tok = t0 + n0 + tid - 1;
    int bsz = (tok >= 0) ? 16 : 0;
    int tokc = (tok >= 0) ? tok : 0;
    hloop(g_outh + ((size_t)b*T_ + t0 + m0 + tid)*D_,
          g_outh + ((size_t)b*T_ + tokc)*D_,
          D_ >> 5, bsz, As, Bs, acc, warp_m, warp_n, lane, tid);

    __half* P = g_Ph + (size_t)(s * B_ + b) * CB_ * CB_;
    #pragma unroll
    for (int mt = 0; mt < 4; mt++)
        #pragma unroll
        for (int h = 0; h < 2; h++) {
            int ii = m0 + warp_m * 64 + mt * 16 + g + h * 8;
            #pragma unroll
            for (int nt = 0; nt < 8; nt++) {
                int jj = n0 + warp_n * 64 + nt * 8 + tq * 2;
                float c0 = (ii > jj)     ? acc[mt][nt][h*2+0] * gpow[ii-1-jj] : 0.f;
                float c1 = (ii > jj + 1) ? acc[mt][nt][h*2+1] * gpow[ii-2-jj] : 0.f;
                *(__half2*)(P + (size_t)ii * CB_ + jj) = __floats2half2_rn(c0, c1);
            }
        }
}

// ---------------- batched U: U_s = vTs_s @ koutT_s^T ------------------------
__global__ __launch_bounds__(128, 2) void k_updateU() {
    extern __shared__ __align__(16) __half sm16[];
    __half* As = sm16;
    __half* Bs = sm16 + NKST_ * STAGE_HALFS_;
    int zb = blockIdx.z; int s = zb >> 3; int b = zb & 7;
    int t0 = s * CB_;
    int tid = threadIdx.x;
    int m0 = blockIdx.y * 128, n0 = blockIdx.x * 128;
    int warp = tid >> 5, lane = tid & 31;
    int warp_m = warp >> 1, warp_n = warp & 1;
    int g = lane >> 2, tq = lane & 3;
    float acc[4][8][4] = {};

    hloop(g_vTs + ((size_t)b*D_ + m0 + tid)*T_ + t0,
          g_koutT + ((size_t)b*D_ + n0 + tid)*T_ + t0,
          CB_ >> 5, 16, As, Bs, acc, warp_m, warp_n, lane, tid);

    __half* U = g_U + (size_t)(s * B_ + b) * DD_;
    #pragma unroll
    for (int mt = 0; mt < 4; mt++)
        #pragma unroll
        for (int h = 0; h < 2; h++) {
            int d = m0 + warp_m * 64 + mt * 16 + g + h * 8;
            #pragma unroll
            for (int nt = 0; nt < 8; nt++) {
                int e = n0 + warp_n * 64 + nt * 8 + tq * 2;
                *(__half2*)(U + (size_t)d * D_ + e) =
                    __floats2half2_rn(acc[mt][nt][h*2+0], acc[mt][nt][h*2+1]);
            }
        }
}

// ---------------- W prefix scan: Whs[s] = sum_{j<s} gC^{s-1-j} U_j ----------
__global__ void k_wscan() {
    int b = blockIdx.y;
    size_t off0 = (size_t)b * DD_ + (size_t)blockIdx.x * 8192;
    int tid = threadIdx.x;
    float gC = __expf((float)CB_ * g_consts[0]);
    float W[32] = {};
    for (int s = 0; s < NSTEP_; s++) {
        size_t so = (size_t)(s * B_) * DD_ + off0;
        #pragma unroll
        for (int k = 0; k < 4; k++) {
            size_t o = so + (size_t)k * 2048 + tid * 8;
            __half2 h0 = __floats2half2_rn(W[k*8+0], W[k*8+1]);
            __half2 h1 = __floats2half2_rn(W[k*8+2], W[k*8+3]);
            __half2 h2 = __floats2half2_rn(W[k*8+4], W[k*8+5]);
            __half2 h3 = __floats2half2_rn(W[k*8+6], W[k*8+7]);
            uint4 pack;
            pack.x = *(uint32_t*)&h0; pack.y = *(uint32_t*)&h1;
            pack.z = *(uint32_t*)&h2; pack.w = *(uint32_t*)&h3;
            *(uint4*)(g_Whs + o) = pack;
            uint4 u = *(const uint4*)(g_U + o);
            __half2 u0 = *(__half2*)&u.x, u1 = *(__half2*)&u.y;
            __half2 u2 = *(__half2*)&u.z, u3 = *(__half2*)&u.w;
            float2 f0 = __half22float2(u0), f1 = __half22float2(u1);
            float2 f2 = __half22float2(u2), f3 = __half22float2(u3);
            W[k*8+0] = gC*W[k*8+0] + f0.x; W[k*8+1] = gC*W[k*8+1] + f0.y;
            W[k*8+2] = gC*W[k*8+2] + f1.x; W[k*8+3] = gC*W[k*8+3] + f1.y;
            W[k*8+4] = gC*W[k*8+4] + f2.x; W[k*8+5] = gC*W[k*8+5] + f2.y;
            W[k*8+6] = gC*W[k*8+6] + f3.x; W[k*8+7] = gC*W[k*8+7] + f3.y;
        }
    }
}

// ---------------- batched reads: inter + intra fused ------------------------
// reads[t0+i, d] = gamma^i * sum_e out[t0+i,e] Whs[s][d,e]  +  sum_j P[i,j] vT[d,j]
__global__ __launch_bounds__(128, 2) void k_readsall() {
    extern __shared__ __align__(16) __half sm16[];
    __half* As = sm16;
    __half* Bs = sm16 + NKST_ * STAGE_HALFS_;
    int zb = blockIdx.z; int s = zb >> 3; int b = zb & 7;
    int t0 = s * CB_;
    int tid = threadIdx.x;
    int m0 = blockIdx.y * 128, n0 = blockIdx.x * 128;   // m over CB, n over D
    int warp = tid >> 5, lane = tid & 31;
    int warp_m = warp >> 1, warp_n = warp & 1;
    int g = lane >> 2, tq = lane & 3;
    float lg = g_consts[0];
    float acc[4][8][4] = {};

    // phase 1: inter = out @ Whs[s]^T
    hloop(g_outh + ((size_t)b*T_ + t0 + m0 + tid)*D_,
          g_Whs + (size_t)(s * B_ + b) * DD_ + (size_t)(n0 + tid)*D_,
          D_ >> 5, 16, As, Bs, acc, warp_m, warp_n, lane, tid);

    // scale by gamma^i
    #pragma unroll
    for (int mt = 0; mt < 4; mt++)
        #pragma unroll
        for (int h = 0; h < 2; h++) {
            int mi = m0 + warp_m * 64 + mt * 16 + g + h * 8;
            float sc = __expf((float)mi * lg);
            #pragma unroll
            for (int nt = 0; nt < 8; nt++) {
                acc[mt][nt][h*2+0] *= sc;
                acc[mt][nt][h*2+1] *= sc;
            }
        }

    // phase 2: intra = P @ vT^T
    hloop(g_Ph + (size_t)(s * B_ + b) * CB_ * CB_ + (size_t)(m0 + tid) * CB_,
          g_vT + ((size_t)b*D_ + n0 + tid)*T_ + t0,
          CB_ >> 5, 16, As, Bs, acc, warp_m, warp_n, lane, tid);

    #pragma unroll
    for (int mt = 0; mt < 4; mt++)
        #pragma unroll
        for (int h = 0; h < 2; h++) {
            int mi = m0 + warp_m * 64 + mt * 16 + g + h * 8;
            size_t row = ((size_t)b * T_ + t0 + mi) * D_;
            #pragma unroll
            for (int nt = 0; nt < 8; nt++) {
                int ni = n0 + warp_n * 64 + nt * 8 + tq * 2;
                *(__half2*)(g_readsh + row + ni) =
                    __floats2half2_rn(acc[mt][nt][h*2+0], acc[mt][nt][h*2+1]);
            }
        }
}

// ---------------- launch ----------------------------------------------------
extern "C" void kernel_launch(void* const* d_in, const int* in_sizes, int n_in,
                              void* d_out, int out_size) {
    const float* x         = (const float*)d_in[0];
    const float* norm_w    = (const float*)d_in[1];
    const float* proj_w    = (const float*)d_in[2];
    const float* gate_w    = (const float*)d_in[3];
    const float* conv_w    = (const float*)d_in[4];
    const float* conv_b    = (const float*)d_in[5];
    const float* out_proj  = (const float*)d_in[6];
    const float* write_w   = (const float*)d_in[7];
    const float* read_w    = (const float*)d_in[8];
    const float* decay     = (const float*)d_in[9];
    const float* log_alpha = (const float*)d_in[10];
    float* out = (float*)d_out;

    float* p_out;
    __half *p_xnh, *p_valh, *p_gateh, *p_hh, *p_outh, *p_vh, *p_readsh, *p_wh;
    cudaGetSymbolAddress((void**)&p_out,    g_out);
    cudaGetSymbolAddress((void**)&p_xnh,    g_xnh);
    cudaGetSymbolAddress((void**)&p_valh,   g_valh);
    cudaGetSymbolAddress((void**)&p_gateh,  g_gateh);
    cudaGetSymbolAddress((void**)&p_hh,     g_hh);
    cudaGetSymbolAddress((void**)&p_outh,   g_outh);
    cudaGetSymbolAddress((void**)&p_vh,     g_vh);
    cudaGetSymbolAddress((void**)&p_readsh, g_readsh);
    cudaGetSymbolAddress((void**)&p_wh,     g_wh);
    __half* wh_proj  = p_wh;
    __half* wh_gate  = p_wh + 1179648;
    __half* wh_outp  = p_wh + 2359296;
    __half* wh_write = p_wh + 3538944;
    __half* wh_read  = p_wh + 4128768;

    static int smem_set = 0;
    if (!smem_set) {
        cudaFuncSetAttribute(k_hgemm16, cudaFuncAttributeMaxDynamicSharedMemorySize, GSM_);
        cudaFuncSetAttribute(k_pchunk,  cudaFuncAttributeMaxDynamicSharedMemorySize, GSM_);
        cudaFuncSetAttribute(k_updateU, cudaFuncAttributeMaxDynamicSharedMemorySize, GSM_);
        cudaFuncSetAttribute(k_readsall,cudaFuncAttributeMaxDynamicSharedMemorySize, GSM_);
        smem_set = 1;
    }

    k_consts<<<1, 1>>>(decay, log_alpha);
    k_h2<<<(DI_*D_/2+255)/256, 256>>>(proj_w,   wh_proj,  DI_*D_/2);
    k_h2<<<(DI_*D_/2+255)/256, 256>>>(gate_w,   wh_gate,  DI_*D_/2);
    k_h2<<<(DI_*D_/2+255)/256, 256>>>(out_proj, wh_outp,  D_*DI_/2);
    k_h2<<<(D_*D_/2+255)/256,  256>>>(write_w,  wh_write, D_*D_/2);
    k_h2<<<(D_*D_/2+255)/256,  256>>>(read_w,   wh_read,  D_*D_/2);
    k_xnorm<<<M_/8, 256>>>(x, norm_w);

    // val(fp16) = xn @ proj^T ; gate(fp16) = silu(xn @ gate^T)
    k_hgemm16<<<dim3(DI_/128, M_/128), 128, GSM_>>>(
        p_xnh, wh_proj, nullptr, p_valh, DI_, D_, 0, nullptr, nullptr);
    k_hgemm16<<<dim3(DI_/128, M_/128), 128, GSM_>>>(
        p_xnh, wh_gate, nullptr, p_gateh, DI_, D_, 1, nullptr, nullptr);
    // h(fp16) = silu(conv(val)+b) * gate
    k_conv<<<dim3(DI_/256, T_/8, B_), 256>>>(conv_w, conv_b);
    // out = h @ out_proj^T  (fp32 + fp16)
    k_hgemm16<<<dim3(D_/128, M_/128), 128, GSM_>>>(
        p_hh, wh_outp, p_out, p_outh, D_, DI_, 0, nullptr, nullptr);
    // v(fp16) = out @ write^T
    k_hgemm16<<<dim3(D_/128, M_/128), 128, GSM_>>>(
        p_outh, wh_write, nullptr, p_vh, D_, D_, 0, nullptr, nullptr);

    // transposed fp16 operand copies
    k_transV<<<dim3(T_/32, D_/32, B_), 256>>>();
    k_transK<<<dim3(T_/32, D_/32, B_), 256>>>();

    // fully-parallel chunk work
    k_pchunk <<<dim3(CB_/128, CB_/128, NSTEP_*B_), 128, GSM_>>>();
    k_updateU<<<dim3(D_/128,  D_/128,  NSTEP_*B_), 128, GSM_>>>();

    // prefix scan of W snapshots
    k_wscan<<<dim3((int)(DD_/8192), B_), 256>>>();

    // fused inter+intra reads (one wide launch)
    k_readsall<<<dim3(D_/128, CB_/128, NSTEP_*B_), 128, GSM_>>>();

    // final: y = x + out + alpha * (reads @ read^T)
    k_hgemm16<<<dim3(D_/128, M_/128), 128, GSM_>>>(
        p_readsh, wh_read, out, nullptr, D_, D_, 2, x, p_out);
}

// round 12
// speedup vs baseline: 1.2722x; 1.2722x over previous
#include <cuda_runtime.h>
#include <cuda_fp16.h>
#include <math.h>
#include <stdint.h>

#define B_ 8
#define T_ 4096
#define D_ 768
#define DI_ 1536
#define M_ (B_*T_)          // 32768 rows
#define CB_ 256             // chunk
#define NSTEP_ (T_/CB_)     // 16
#define DD_ ((size_t)D_*D_)
#define SROW_ 40            // fp16 SMEM row stride (halfs)
#define NKST_ 4             // cp.async stages
#define STAGE_HALFS_ (128*SROW_)
#define GSM_ (2*NKST_*STAGE_HALFS_*2)   // 81920 bytes dynamic SMEM

// ---------------- scratch ---------------------------------------------------
__device__ float  g_out[(size_t)M_*D_];
__device__ __half g_xnh[(size_t)M_*D_];
__device__ __half g_valh[(size_t)M_*DI_];
__device__ __half g_gateh[(size_t)M_*DI_];
__device__ __half g_hh[(size_t)M_*DI_];
__device__ __half g_outh[(size_t)M_*D_];
__device__ __half g_vh[(size_t)M_*D_];
__device__ __half g_vT[(size_t)M_*D_];     // [b][d][t]
__device__ __half g_vTs[(size_t)M_*D_];    // [b][d][t] * gamma^(CB-1-(t%CB))
__device__ __half g_koutT[(size_t)M_*D_];  // [b][e][t] = out[t-1][e]
__device__ __half g_Ph[(size_t)B_*NSTEP_*CB_*CB_];
__device__ __half g_U[(size_t)NSTEP_*B_*D_*D_];    // per-chunk updates
__device__ __half g_Whs[(size_t)NSTEP_*B_*D_*D_];  // W prefix snapshots
__device__ __half g_readsh[(size_t)M_*D_];
__device__ __half g_wh[4718592];           // fp16 weight copies (contiguous)
__device__ float g_consts[2];              // [0]=log(gamma), [1]=alpha

// ---------------- asm helpers ------------------------------------------------
#define CP_ASYNC16(dst, src) \
    asm volatile("cp.async.ca.shared.global [%0], [%1], 16;" :: "r"(dst), "l"(src))
#define CP_ASYNC16Z(dst, src, sz) \
    asm volatile("cp.async.ca.shared.global [%0], [%1], 16, %2;" :: "r"(dst), "l"(src), "r"(sz))
#define CP_COMMIT()  asm volatile("cp.async.commit_group;" ::: "memory")
#define CP_WAIT2()   asm volatile("cp.async.wait_group 2;" ::: "memory")

#define LDSM4(r, addr) \
    asm volatile("ldmatrix.sync.aligned.m8n8.x4.shared.b16 {%0,%1,%2,%3}, [%4];" \
        : "=r"((r)[0]), "=r"((r)[1]), "=r"((r)[2]), "=r"((r)[3]) : "r"(addr))

__device__ __forceinline__ void mma_h(float* c, const uint32_t* a, const uint32_t* b) {
    asm volatile(
        "mma.sync.aligned.m16n8k16.row.col.f32.f16.f16.f32 "
        "{%0,%1,%2,%3}, {%4,%5,%6,%7}, {%8,%9}, {%0,%1,%2,%3};"
        : "+f"(c[0]), "+f"(c[1]), "+f"(c[2]), "+f"(c[3])
        : "r"(a[0]), "r"(a[1]), "r"(a[2]), "r"(a[3]), "r"(b[0]), "r"(b[1]));
}

// ---------------- shared pipelined fp16 mainloop (32x64 warp tiles) ---------
// 256 threads, 8 warps as 4(m) x 2(n). BK=32/stage, 4-stage cp.async ring.
__device__ __forceinline__ void hloop(
    const __half* __restrict__ Ag, const __half* __restrict__ Bg,
    int nk, int bsz, __half* As, __half* Bs, float acc[2][8][4],
    int warp_m, int warp_n, int lane, int tid)
{
    int lrow = tid >> 1, lc = (tid & 1) * 2;
    uint32_t aBase = (uint32_t)__cvta_generic_to_shared(As);
    uint32_t bBase = (uint32_t)__cvta_generic_to_shared(Bs);
    uint32_t dA = aBase + (lrow * SROW_ + lc * 8) * 2;
    uint32_t dB = bBase + (lrow * SROW_ + lc * 8) * 2;

    auto ISSUE = [&](int s) {
        uint32_t offs = (uint32_t)(s % NKST_) * (STAGE_HALFS_ * 2);
        const __half* ag = Ag + s * 32;
        const __half* bg = Bg + s * 32;
        CP_ASYNC16(dA + offs, ag);
        CP_ASYNC16(dA + offs + 16, ag + 8);
        CP_ASYNC16Z(dB + offs, bg, bsz);
        CP_ASYNC16Z(dB + offs + 16, bg + 8, bsz);
    };

    ISSUE(0); CP_COMMIT();
    if (nk > 1) ISSUE(1);
    CP_COMMIT();
    if (nk > 2) ISSUE(2);
    CP_COMMIT();

    int lr = lane & 15, lk = (lane >> 4) << 3;
    for (int s = 0; s < nk; s++) {
        CP_WAIT2();
        __syncthreads();
        if (s + 3 < nk) ISSUE(s + 3);
        CP_COMMIT();

        uint32_t st = (uint32_t)(s % NKST_) * (STAGE_HALFS_ * 2);
        uint32_t aS = aBase + st, bS = bBase + st;
        #pragma unroll
        for (int ks = 0; ks < 32; ks += 16) {
            uint32_t a0 = aS + ((warp_m * 32 + lr) * SROW_ + ks + lk) * 2;
            uint32_t af0[4], af1[4];
            LDSM4(af0, a0);
            LDSM4(af1, a0 + 16 * SROW_ * 2);
            #pragma unroll
            for (int p = 0; p < 4; p++) {
                uint32_t bb = bS + ((warp_n * 64 + p * 16 + lr) * SROW_ + ks + lk) * 2;
                uint32_t bf[4];
                LDSM4(bf, bb);
                uint32_t be[2] = { bf[0], bf[2] };
                uint32_t bo[2] = { bf[1], bf[3] };
                mma_h(acc[0][2*p],   af0, be);
                mma_h(acc[1][2*p],   af1, be);
                mma_h(acc[0][2*p+1], af0, bo);
                mma_h(acc[1][2*p+1], af1, bo);
            }
        }
    }
    __syncthreads();   // protect SMEM for any subsequent phase
}

// ---------------- small kernels ---------------------------------------------
__global__ void k_consts(const float* __restrict__ decay,
                         const float* __restrict__ log_alpha) {
    float g = 1.f / (1.f + expf(-decay[0]));
    g_consts[0] = logf(g);
    g_consts[1] = expf(log_alpha[0]);
}

// merged fp32->fp16 conversion of all 5 weight matrices into contiguous g_wh
__global__ void k_h2all(const float* __restrict__ w0, const float* __restrict__ w1,
                        const float* __restrict__ w2, const float* __restrict__ w3,
                        const float* __restrict__ w4) {
    int i = blockIdx.x * 256 + threadIdx.x;     // pair index, total 2359296
    int e = i * 2;
    const float* src;
    int local;
    if (e < 1179648)      { src = w0; local = e; }
    else if (e < 2359296) { src = w1; local = e - 1179648; }
    else if (e < 3538944) { src = w2; local = e - 2359296; }
    else if (e < 4128768) { src = w3; local = e - 3538944; }
    else                  { src = w4; local = e - 4128768; }
    float2 v = *(const float2*)(src + local);
    *(__half2*)(g_wh + e) = __floats2half2_rn(v.x, v.y);
}

__global__ void k_xnorm(const float* __restrict__ x, const float* __restrict__ nw) {
    int warp = threadIdx.x >> 5, lane = threadIdx.x & 31;
    int row = blockIdx.x * 8 + warp;
    const float* p = x + (size_t)row * D_;
    float s = 0.f;
    #pragma unroll
    for (int i = lane; i < D_; i += 32) { float v = p[i]; s += v * v; }
    #pragma unroll
    for (int o = 16; o; o >>= 1) s += __shfl_xor_sync(0xffffffffu, s, o);
    float inv = rsqrtf(s * (1.f / D_) + 1e-5f);
    __half* q = g_xnh + (size_t)row * D_;
    #pragma unroll
    for (int i = lane; i < D_; i += 32) q[i] = __float2half(p[i] * inv * nw[i]);
}

// fp16 conv, vectorized over channel pairs: h = silu(conv(val)+b) * gate
__global__ void k_conv(const float* __restrict__ cw, const float* __restrict__ cb) {
    int e2 = blockIdx.x * 256 + threadIdx.x;    // pair index 0..DI/2-1
    int e0 = e2 * 2;
    int t0 = blockIdx.y * 8;
    int b = blockIdx.z;
    size_t base = (((size_t)b * T_ + t0) * DI_ + e0) >> 1;   // __half2 index
    const __half2* valh2 = (const __half2*)g_valh;
    const __half2* gateh2 = (const __half2*)g_gateh;
    __half2* hh2 = (__half2*)g_hh;
    float4 wa = *(const float4*)(cw + e0 * 4);       // w[e0][0..3]
    float4 wb = *(const float4*)(cw + e0 * 4 + 4);   // w[e0+1][0..3]
    float2 bias = *(const float2*)(cb + e0);
    float2 h0 = make_float2(0.f, 0.f), h1 = h0, h2v = h0;
    if (t0 >= 3) h0 = __half22float2(valh2[base - 3*(DI_/2)]);
    if (t0 >= 2) h1 = __half22float2(valh2[base - 2*(DI_/2)]);
    if (t0 >= 1) h2v = __half22float2(valh2[base - 1*(DI_/2)]);
    #pragma unroll
    for (int j = 0; j < 8; j++) {
        size_t idx = base + (size_t)j * (DI_/2);
        float2 cur = __half22float2(valh2[idx]);
        float vx = bias.x + wa.x*h0.x + wa.y*h1.x + wa.z*h2v.x + wa.w*cur.x;
        float vy = bias.y + wb.x*h0.y + wb.y*h1.y + wb.z*h2v.y + wb.w*cur.y;
        h0 = h1; h1 = h2v; h2v = cur;
        float sx = vx / (1.f + __expf(-vx));
        float sy = vy / (1.f + __expf(-vy));
        float2 gt = __half22float2(gateh2[idx]);
        hh2[idx] = __floats2half2_rn(sx * gt.x, sy * gt.y);
    }
}

// 32x32 tile transposes -------------------------------------------------------
__global__ void k_transV() {
    __shared__ __half sm[32][33];
    int b = blockIdx.z;
    int t0 = blockIdx.x * 32, d0 = blockIdx.y * 32;
    int tx = threadIdx.x & 31, ty = threadIdx.x >> 5;
    #pragma unroll
    for (int j = 0; j < 4; j++)
        sm[ty + j*8][tx] = g_vh[((size_t)b*T_ + t0 + ty + j*8)*D_ + d0 + tx];
    __syncthreads();
    float gw = __expf((float)(CB_ - 1 - ((t0 + tx) % CB_)) * g_consts[0]);
    #pragma unroll
    for (int j = 0; j < 4; j++) {
        size_t o = ((size_t)b*D_ + d0 + ty + j*8)*T_ + t0 + tx;
        __half v = sm[tx][ty + j*8];
        g_vT[o] = v;
        g_vTs[o] = __float2half(__half2float(v) * gw);
    }
}

__global__ void k_transK() {
    __shared__ __half sm[32][33];
    int b = blockIdx.z;
    int t0 = blockIdx.x * 32, d0 = blockIdx.y * 32;
    int tx = threadIdx.x & 31, ty = threadIdx.x >> 5;
    #pragma unroll
    for (int j = 0; j < 4; j++) {
        int t = t0 + ty + j*8;
        sm[ty + j*8][tx] = (t > 0)
            ? g_outh[((size_t)b*T_ + t - 1)*D_ + d0 + tx] : __float2half(0.f);
    }
    __syncthreads();
    #pragma unroll
    for (int j = 0; j < 4; j++)
        g_koutT[((size_t)b*D_ + d0 + ty + j*8)*T_ + t0 + tx] = sm[tx][ty + j*8];
}

// ---------------- dense fp16 TN GEMM -----------------------------------------
// mode 0: acc ; 1: silu ; 2: add1+add2+alpha*acc. C (fp32) / Ch (fp16) optional.
__global__ __launch_bounds__(256, 2) void k_hgemm16(
    const __half* __restrict__ A, const __half* __restrict__ Bm,
    float* __restrict__ C, __half* __restrict__ Ch, int N, int K,
    int mode, const float* __restrict__ add1, const float* __restrict__ add2)
{
    extern __shared__ __align__(16) __half sm16[];
    __half* As = sm16;
    __half* Bs = sm16 + NKST_ * STAGE_HALFS_;
    int tid = threadIdx.x;
    int m0 = blockIdx.y * 128, n0 = blockIdx.x * 128;
    int warp = tid >> 5, lane = tid & 31;
    int warp_m = warp >> 1, warp_n = warp & 1;
    int g = lane >> 2, tq = lane & 3;
    int lrow = tid >> 1, lc = (tid & 1) * 2;
    float acc[2][8][4] = {};

    hloop(A + (size_t)(m0 + lrow) * K + lc * 8,
          Bm + (size_t)(n0 + lrow) * K + lc * 8,
          K >> 5, 16, As, Bs, acc, warp_m, warp_n, lane, tid);

    float alpha = (mode == 2) ? g_consts[1] : 0.f;
    #pragma unroll
    for (int mt = 0; mt < 2; mt++)
        #pragma unroll
        for (int h = 0; h < 2; h++) {
            int mi = m0 + warp_m * 32 + mt * 16 + g + h * 8;
            size_t row = (size_t)mi * N;
            #pragma unroll
            for (int nt = 0; nt < 8; nt++) {
                int ni = n0 + warp_n * 64 + nt * 8 + tq * 2;
                float c0 = acc[mt][nt][h*2 + 0];
                float c1 = acc[mt][nt][h*2 + 1];
                if (mode == 1) {
                    c0 = c0 / (1.f + __expf(-c0));
                    c1 = c1 / (1.f + __expf(-c1));
                } else if (mode == 2) {
                    float2 a1 = *(const float2*)(add1 + row + ni);
                    float2 a2 = *(const float2*)(add2 + row + ni);
                    c0 = a1.x + a2.x + alpha * c0;
                    c1 = a1.y + a2.y + alpha * c1;
                }
                if (C)  *(float2*)(C + row + ni) = make_float2(c0, c1);
                if (Ch) *(__half2*)(Ch + row + ni) = __floats2half2_rn(c0, c1);
            }
        }
}

// ---------------- batched pchunk: P = mask(r@k^T) -> fp16 -------------------
__global__ __launch_bounds__(256, 2) void k_pchunk() {
    extern __shared__ __align__(16) __half sm16[];
    __half* As = sm16;
    __half* Bs = sm16 + NKST_ * STAGE_HALFS_;
    __shared__ float gpow[256];
    int zb = blockIdx.z; int s = zb >> 3; int b = zb & 7;
    int t0 = s * CB_;
    int tid = threadIdx.x;
    int m0 = blockIdx.y * 128, n0 = blockIdx.x * 128;
    int warp = tid >> 5, lane = tid & 31;
    int warp_m = warp >> 1, warp_n = warp & 1;
    int g = lane >> 2, tq = lane & 3;
    int lrow = tid >> 1, lc = (tid & 1) * 2;
    float acc[2][8][4] = {};
    gpow[tid] = __expf((float)tid * g_consts[0]);

    int tok = t0 + n0 + lrow - 1;
    int bsz = (tok >= 0) ? 16 : 0;
    int tokc = (tok >= 0) ? tok : 0;
    hloop(g_outh + ((size_t)b*T_ + t0 + m0 + lrow)*D_ + lc*8,
          g_outh + ((size_t)b*T_ + tokc)*D_ + lc*8,
          D_ >> 5, bsz, As, Bs, acc, warp_m, warp_n, lane, tid);

    __half* P = g_Ph + (size_t)(s * B_ + b) * CB_ * CB_;
    #pragma unroll
    for (int mt = 0; mt < 2; mt++)
        #pragma unroll
        for (int h = 0; h < 2; h++) {
            int ii = m0 + warp_m * 32 + mt * 16 + g + h * 8;
            #pragma unroll
            for (int nt = 0; nt < 8; nt++) {
                int jj = n0 + warp_n * 64 + nt * 8 + tq * 2;
                float c0 = (ii > jj)     ? acc[mt][nt][h*2+0] * gpow[ii-1-jj] : 0.f;
                float c1 = (ii > jj + 1) ? acc[mt][nt][h*2+1] * gpow[ii-2-jj] : 0.f;
                *(__half2*)(P + (size_t)ii * CB_ + jj) = __floats2half2_rn(c0, c1);
            }
        }
}

// ---------------- batched U: U_s = vTs_s @ koutT_s^T ------------------------
__global__ __launch_bounds__(256, 2) void k_updateU() {
    extern __shared__ __align__(16) __half sm16[];
    __half* As = sm16;
    __half* Bs = sm16 + NKST_ * STAGE_HALFS_;
    int zb = blockIdx.z; int s = zb >> 3; int b = zb & 7;
    int t0 = s * CB_;
    int tid = threadIdx.x;
    int m0 = blockIdx.y * 128, n0 = blockIdx.x * 128;
    int warp = tid >> 5, lane = tid & 31;
    int warp_m = warp >> 1, warp_n = warp & 1;
    int g = lane >> 2, tq = lane & 3;
    int lrow = tid >> 1, lc = (tid & 1) * 2;
    float acc[2][8][4] = {};

    hloop(g_vTs + ((size_t)b*D_ + m0 + lrow)*T_ + t0 + lc*8,
          g_koutT + ((size_t)b*D_ + n0 + lrow)*T_ + t0 + lc*8,
          CB_ >> 5, 16, As, Bs, acc, warp_m, warp_n, lane, tid);

    __half* U = g_U + (size_t)(s * B_ + b) * DD_;
    #pragma unroll
    for (int mt = 0; mt < 2; mt++)
        #pragma unroll
        for (int h = 0; h < 2; h++) {
            int d = m0 + warp_m * 32 + mt * 16 + g + h * 8;
            #pragma unroll
            for (int nt = 0; nt < 8; nt++) {
                int e = n0 + warp_n * 64 + nt * 8 + tq * 2;
                *(__half2*)(U + (size_t)d * D_ + e) =
                    __floats2half2_rn(acc[mt][nt][h*2+0], acc[mt][nt][h*2+1]);
            }
        }
}

// ---------------- W prefix scan: Whs[s] = sum_{j<s} gC^{s-1-j} U_j ----------
__global__ void k_wscan() {
    int b = blockIdx.y;
    size_t off0 = (size_t)b * DD_ + (size_t)blockIdx.x * 8192;
    int tid = threadIdx.x;
    float gC = __expf((float)CB_ * g_consts[0]);
    float W[32] = {};
    for (int s = 0; s < NSTEP_; s++) {
        size_t so = (size_t)(s * B_) * DD_ + off0;
        #pragma unroll
        for (int k = 0; k < 4; k++) {
            size_t o = so + (size_t)k * 2048 + tid * 8;
            __half2 h0 = __floats2half2_rn(W[k*8+0], W[k*8+1]);
            __half2 h1 = __floats2half2_rn(W[k*8+2], W[k*8+3]);
            __half2 h2 = __floats2half2_rn(W[k*8+4], W[k*8+5]);
            __half2 h3 = __floats2half2_rn(W[k*8+6], W[k*8+7]);
            uint4 pack;
            pack.x = *(uint32_t*)&h0; pack.y = *(uint32_t*)&h1;
            pack.z = *(uint32_t*)&h2; pack.w = *(uint32_t*)&h3;
            *(uint4*)(g_Whs + o) = pack;
            uint4 u = *(const uint4*)(g_U + o);
            __half2 u0 = *(__half2*)&u.x, u1 = *(__half2*)&u.y;
            __half2 u2 = *(__half2*)&u.z, u3 = *(__half2*)&u.w;
            float2 f0 = __half22float2(u0), f1 = __half22float2(u1);
            float2 f2 = __half22float2(u2), f3 = __half22float2(u3);
            W[k*8+0] = gC*W[k*8+0] + f0.x; W[k*8+1] = gC*W[k*8+1] + f0.y;
            W[k*8+2] = gC*W[k*8+2] + f1.x; W[k*8+3] = gC*W[k*8+3] + f1.y;
            W[k*8+4] = gC*W[k*8+4] + f2.x; W[k*8+5] = gC*W[k*8+5] + f2.y;
            W[k*8+6] = gC*W[k*8+6] + f3.x; W[k*8+7] = gC*W[k*8+7] + f3.y;
        }
    }
}

// ---------------- batched reads: inter + intra fused ------------------------
// reads[t0+i, d] = gamma^i * sum_e out[t0+i,e] Whs[s][d,e]  +  sum_j P[i,j] vT[d,j]
__global__ __launch_bounds__(256, 2) void k_readsall() {
    extern __shared__ __align__(16) __half sm16[];
    __half* As = sm16;
    __half* Bs = sm16 + NKST_ * STAGE_HALFS_;
    int zb = blockIdx.z; int s = zb >> 3; int b = zb & 7;
    int t0 = s * CB_;
    int tid = threadIdx.x;
    int m0 = blockIdx.y * 128, n0 = blockIdx.x * 128;   // m over CB, n over D
    int warp = tid >> 5, lane = tid & 31;
    int warp_m = warp >> 1, warp_n = warp & 1;
    int g = lane >> 2, tq = lane & 3;
    int lrow = tid >> 1, lc = (tid & 1) * 2;
    float lg = g_consts[0];
    float acc[2][8][4] = {};

    // phase 1: inter = out @ Whs[s]^T
    hloop(g_outh + ((size_t)b*T_ + t0 + m0 + lrow)*D_ + lc*8,
          g_Whs + (size_t)(s * B_ + b) * DD_ + (size_t)(n0 + lrow)*D_ + lc*8,
          D_ >> 5, 16, As, Bs, acc, warp_m, warp_n, lane, tid);

    // scale by gamma^i
    #pragma unroll
    for (int mt = 0; mt < 2; mt++)
        #pragma unroll
        for (int h = 0; h < 2; h++) {
            int mi = m0 + warp_m * 32 + mt * 16 + g + h * 8;
            float sc = __expf((float)mi * lg);
            #pragma unroll
            for (int nt = 0; nt < 8; nt++) {
                acc[mt][nt][h*2+0] *= sc;
                acc[mt][nt][h*2+1] *= sc;
            }
        }

    // phase 2: intra = P @ vT^T
    hloop(g_Ph + (size_t)(s * B_ + b) * CB_ * CB_ + (size_t)(m0 + lrow) * CB_ + lc*8,
          g_vT + ((size_t)b*D_ + n0 + lrow)*T_ + t0 + lc*8,
          CB_ >> 5, 16, As, Bs, acc, warp_m, warp_n, lane, tid);

    #pragma unroll
    for (int mt = 0; mt < 2; mt++)
        #pragma unroll
        for (int h = 0; h < 2; h++) {
            int mi = m0 + warp_m * 32 + mt * 16 + g + h * 8;
            size_t row = ((size_t)b * T_ + t0 + mi) * D_;
            #pragma unroll
            for (int nt = 0; nt < 8; nt++) {
                int ni = n0 + warp_n * 64 + nt * 8 + tq * 2;
                *(__half2*)(g_readsh + row + ni) =
                    __floats2half2_rn(acc[mt][nt][h*2+0], acc[mt][nt][h*2+1]);
            }
        }
}

// ---------------- launch ----------------------------------------------------
extern "C" void kernel_launch(void* const* d_in, const int* in_sizes, int n_in,
                              void* d_out, int out_size) {
    const float* x         = (const float*)d_in[0];
    const float* norm_w    = (const float*)d_in[1];
    const float* proj_w    = (const float*)d_in[2];
    const float* gate_w    = (const float*)d_in[3];
    const float* conv_w    = (const float*)d_in[4];
    const float* conv_b    = (const float*)d_in[5];
    const float* out_proj  = (const float*)d_in[6];
    const float* write_w   = (const float*)d_in[7];
    const float* read_w    = (const float*)d_in[8];
    const float* decay     = (const float*)d_in[9];
    const float* log_alpha = (const float*)d_in[10];
    float* out = (float*)d_out;

    float* p_out;
    __half *p_xnh, *p_valh, *p_gateh, *p_hh, *p_outh, *p_vh, *p_readsh, *p_wh;
    cudaGetSymbolAddress((void**)&p_out,    g_out);
    cudaGetSymbolAddress((void**)&p_xnh,    g_xnh);
    cudaGetSymbolAddress((void**)&p_valh,   g_valh);
    cudaGetSymbolAddress((void**)&p_gateh,  g_gateh);
    cudaGetSymbolAddress((void**)&p_hh,     g_hh);
    cudaGetSymbolAddress((void**)&p_outh,   g_outh);
    cudaGetSymbolAddress((void**)&p_vh,     g_vh);
    cudaGetSymbolAddress((void**)&p_readsh, g_readsh);
    cudaGetSymbolAddress((void**)&p_wh,     g_wh);
    __half* wh_proj  = p_wh;
    __half* wh_gate  = p_wh + 1179648;
    __half* wh_outp  = p_wh + 2359296;
    __half* wh_write = p_wh + 3538944;
    __half* wh_read  = p_wh + 4128768;

    static int smem_set = 0;
    if (!smem_set) {
        cudaFuncSetAttribute(k_hgemm16, cudaFuncAttributeMaxDynamicSharedMemorySize, GSM_);
        cudaFuncSetAttribute(k_pchunk,  cudaFuncAttributeMaxDynamicSharedMemorySize, GSM_);
        cudaFuncSetAttribute(k_updateU, cudaFuncAttributeMaxDynamicSharedMemorySize, GSM_);
        cudaFuncSetAttribute(k_readsall,cudaFuncAttributeMaxDynamicSharedMemorySize, GSM_);
        smem_set = 1;
    }

    k_consts<<<1, 1>>>(decay, log_alpha);
    k_h2all<<<2359296/256, 256>>>(proj_w, gate_w, out_proj, write_w, read_w);
    k_xnorm<<<M_/8, 256>>>(x, norm_w);

    // val(fp16) = xn @ proj^T ; gate(fp16) = silu(xn @ gate^T)
    k_hgemm16<<<dim3(DI_/128, M_/128), 256, GSM_>>>(
        p_xnh, wh_proj, nullptr, p_valh, DI_, D_, 0, nullptr, nullptr);
    k_hgemm16<<<dim3(DI_/128, M_/128), 256, GSM_>>>(
        p_xnh, wh_gate, nullptr, p_gateh, DI_, D_, 1, nullptr, nullptr);
    // h(fp16) = silu(conv(val)+b) * gate
    k_conv<<<dim3(DI_/512, T_/8, B_), 256>>>(conv_w, conv_b);
    // out = h @ out_proj^T  (fp32 + fp16)
    k_hgemm16<<<dim3(D_/128, M_/128), 256, GSM_>>>(
        p_hh, wh_outp, p_out, p_outh, D_, DI_, 0, nullptr, nullptr);
    // v(fp16) = out @ write^T
    k_hgemm16<<<dim3(D_/128, M_/128), 256, GSM_>>>(
        p_outh, wh_write, nullptr, p_vh, D_, D_, 0, nullptr, nullptr);

    // transposed fp16 operand copies
    k_transV<<<dim3(T_/32, D_/32, B_), 256>>>();
    k_transK<<<dim3(T_/32, D_/32, B_), 256>>>();

    // fully-parallel chunk work
    k_pchunk <<<dim3(CB_/128, CB_/128, NSTEP_*B_), 256, GSM_>>>();
    k_updateU<<<dim3(D_/128,  D_/128,  NSTEP_*B_), 256, GSM_>>>();

    // prefix scan of W snapshots
    k_wscan<<<dim3((int)(DD_/8192), B_), 256>>>();

    // fused inter+intra reads (one wide launch)
    k_readsall<<<dim3(D_/128, CB_/128, NSTEP_*B_), 256, GSM_>>>();

    // final: y = x + out + alpha * (reads @ read^T)
    k_hgemm16<<<dim3(D_/128, M_/128), 256, GSM_>>>(
        p_readsh, wh_read, out, nullptr, D_, D_, 2, x, p_out);
}

// round 14
// speedup vs baseline: 1.3297x; 1.0453x over previous
#include <cuda_runtime.h>
#include <cuda_fp16.h>
#include <math.h>
#include <stdint.h>

#define B_ 8
#define T_ 4096
#define D_ 768
#define DI_ 1536
#define M_ (B_*T_)          // 32768 rows
#define CB_ 256             // chunk
#define NSTEP_ (T_/CB_)     // 16
#define DD_ ((size_t)D_*D_)
#define SROW_ 40            // fp16 SMEM row stride (halfs)
#define NKST_ 3             // cp.async stages
#define STAGE_HALFS_ (128*SROW_)
#define GSM_ (2*NKST_*STAGE_HALFS_*2)   // 61440 bytes dynamic SMEM

// ---------------- scratch ---------------------------------------------------
__device__ float  g_out[(size_t)M_*D_];
__device__ __half g_xnh[(size_t)M_*D_];
__device__ __half g_valh[(size_t)M_*DI_];
__device__ __half g_gateh[(size_t)M_*DI_];
__device__ __half g_hh[(size_t)M_*DI_];
__device__ __half g_outh[(size_t)M_*D_];
__device__ __half g_vh[(size_t)M_*D_];
__device__ __half g_vT[(size_t)M_*D_];     // [b][d][t]
__device__ __half g_vTs[(size_t)M_*D_];    // [b][d][t] * gamma^(CB-1-(t%CB))
__device__ __half g_koutT[(size_t)M_*D_];  // [b][e][t] = out[t-1][e]
__device__ __half g_Ph[(size_t)B_*NSTEP_*CB_*CB_];
__device__ __half g_U[(size_t)NSTEP_*B_*D_*D_];    // per-chunk updates
__device__ __half g_Whs[(size_t)NSTEP_*B_*D_*D_];  // W prefix snapshots
__device__ __half g_readsh[(size_t)M_*D_];
__device__ __half g_wh[4718592];           // fp16 weight copies (contiguous)
__device__ float g_consts[2];              // [0]=log(gamma), [1]=alpha

// ---------------- asm helpers ------------------------------------------------
#define CP_ASYNC16(dst, src) \
    asm volatile("cp.async.cg.shared.global [%0], [%1], 16;" :: "r"(dst), "l"(src))
#define CP_ASYNC16Z(dst, src, sz) \
    asm volatile("cp.async.cg.shared.global [%0], [%1], 16, %2;" :: "r"(dst), "l"(src), "r"(sz))
#define CP_COMMIT()  asm volatile("cp.async.commit_group;" ::: "memory")
#define CP_WAIT1()   asm volatile("cp.async.wait_group 1;" ::: "memory")

#define LDSM4(r, addr) \
    asm volatile("ldmatrix.sync.aligned.m8n8.x4.shared.b16 {%0,%1,%2,%3}, [%4];" \
        : "=r"((r)[0]), "=r"((r)[1]), "=r"((r)[2]), "=r"((r)[3]) : "r"(addr))

__device__ __forceinline__ void mma_h(float* c, const uint32_t* a, const uint32_t* b) {
    asm volatile(
        "mma.sync.aligned.m16n8k16.row.col.f32.f16.f16.f32 "
        "{%0,%1,%2,%3}, {%4,%5,%6,%7}, {%8,%9}, {%0,%1,%2,%3};"
        : "+f"(c[0]), "+f"(c[1]), "+f"(c[2]), "+f"(c[3])
        : "r"(a[0]), "r"(a[1]), "r"(a[2]), "r"(a[3]), "r"(b[0]), "r"(b[1]));
}

// ---------------- shared pipelined fp16 mainloop (32x64 warp tiles) ---------
// 256 threads, 8 warps as 4(m) x 2(n). BK=32/stage, 3-stage cp.async ring.
__device__ __forceinline__ void hloop(
    const __half* __restrict__ Ag, const __half* __restrict__ Bg,
    int nk, int bsz, __half* As, __half* Bs, float acc[2][8][4],
    int warp_m, int warp_n, int lane, int tid)
{
    int lrow = tid >> 1, lc = (tid & 1) * 2;
    uint32_t aBase = (uint32_t)__cvta_generic_to_shared(As);
    uint32_t bBase = (uint32_t)__cvta_generic_to_shared(Bs);
    uint32_t dA = aBase + (lrow * SROW_ + lc * 8) * 2;
    uint32_t dB = bBase + (lrow * SROW_ + lc * 8) * 2;

    auto ISSUE = [&](int s) {
        uint32_t offs = (uint32_t)(s % NKST_) * (STAGE_HALFS_ * 2);
        const __half* ag = Ag + s * 32;
        const __half* bg = Bg + s * 32;
        CP_ASYNC16(dA + offs, ag);
        CP_ASYNC16(dA + offs + 16, ag + 8);
        CP_ASYNC16Z(dB + offs, bg, bsz);
        CP_ASYNC16Z(dB + offs + 16, bg + 8, bsz);
    };

    ISSUE(0); CP_COMMIT();
    if (nk > 1) ISSUE(1);
    CP_COMMIT();

    int lr = lane & 15, lk = (lane >> 4) << 3;
    for (int s = 0; s < nk; s++) {
        CP_WAIT1();
        __syncthreads();
        if (s + 2 < nk) ISSUE(s + 2);
        CP_COMMIT();

        uint32_t st = (uint32_t)(s % NKST_) * (STAGE_HALFS_ * 2);
        uint32_t aS = aBase + st, bS = bBase + st;
        #pragma unroll
        for (int ks = 0; ks < 32; ks += 16) {
            uint32_t a0 = aS + ((warp_m * 32 + lr) * SROW_ + ks + lk) * 2;
            uint32_t af0[4], af1[4];
            LDSM4(af0, a0);
            LDSM4(af1, a0 + 16 * SROW_ * 2);
            #pragma unroll
            for (int p = 0; p < 4; p++) {
                uint32_t bb = bS + ((warp_n * 64 + p * 16 + lr) * SROW_ + ks + lk) * 2;
                uint32_t bf[4];
                LDSM4(bf, bb);
                uint32_t be[2] = { bf[0], bf[2] };
                uint32_t bo[2] = { bf[1], bf[3] };
                mma_h(acc[0][2*p],   af0, be);
                mma_h(acc[1][2*p],   af1, be);
                mma_h(acc[0][2*p+1], af0, bo);
                mma_h(acc[1][2*p+1], af1, bo);
            }
        }
    }
    __syncthreads();   // protect SMEM for any subsequent phase
}

// ---------------- small kernels ---------------------------------------------
__global__ void k_consts(const float* __restrict__ decay,
                         const float* __restrict__ log_alpha) {
    float g = 1.f / (1.f + expf(-decay[0]));
    g_consts[0] = logf(g);
    g_consts[1] = expf(log_alpha[0]);
}

// merged fp32->fp16 conversion of all 5 weight matrices into contiguous g_wh
__global__ void k_h2all(const float* __restrict__ w0, const float* __restrict__ w1,
                        const float* __restrict__ w2, const float* __restrict__ w3,
                        const float* __restrict__ w4) {
    int i = blockIdx.x * 256 + threadIdx.x;     // pair index, total 2359296
    int e = i * 2;
    const float* src;
    int local;
    if (e < 1179648)      { src = w0; local = e; }
    else if (e < 2359296) { src = w1; local = e - 1179648; }
    else if (e < 3538944) { src = w2; local = e - 2359296; }
    else if (e < 4128768) { src = w3; local = e - 3538944; }
    else                  { src = w4; local = e - 4128768; }
    float2 v = *(const float2*)(src + local);
    *(__half2*)(g_wh + e) = __floats2half2_rn(v.x, v.y);
}

__global__ void k_xnorm(const float* __restrict__ x, const float* __restrict__ nw) {
    int warp = threadIdx.x >> 5, lane = threadIdx.x & 31;
    int row = blockIdx.x * 8 + warp;
    const float* p = x + (size_t)row * D_;
    float s = 0.f;
    #pragma unroll
    for (int i = lane; i < D_; i += 32) { float v = p[i]; s += v * v; }
    #pragma unroll
    for (int o = 16; o; o >>= 1) s += __shfl_xor_sync(0xffffffffu, s, o);
    float inv = rsqrtf(s * (1.f / D_) + 1e-5f);
    __half* q = g_xnh + (size_t)row * D_;
    #pragma unroll
    for (int i = lane; i < D_; i += 32) q[i] = __float2half(p[i] * inv * nw[i]);
}

// fp16 conv, vectorized over channel pairs: h = silu(conv(val)+b) * gate
__global__ void k_conv(const float* __restrict__ cw, const float* __restrict__ cb) {
    int e2 = blockIdx.x * 256 + threadIdx.x;    // pair index 0..DI/2-1
    int e0 = e2 * 2;
    int t0 = blockIdx.y * 8;
    int b = blockIdx.z;
    size_t base = (((size_t)b * T_ + t0) * DI_ + e0) >> 1;   // __half2 index
    const __half2* valh2 = (const __half2*)g_valh;
    const __half2* gateh2 = (const __half2*)g_gateh;
    __half2* hh2 = (__half2*)g_hh;
    float4 wa = *(const float4*)(cw + e0 * 4);       // w[e0][0..3]
    float4 wb = *(const float4*)(cw + e0 * 4 + 4);   // w[e0+1][0..3]
    float2 bias = *(const float2*)(cb + e0);
    float2 h0 = make_float2(0.f, 0.f), h1 = h0, h2v = h0;
    if (t0 >= 3) h0 = __half22float2(valh2[base - 3*(DI_/2)]);
    if (t0 >= 2) h1 = __half22float2(valh2[base - 2*(DI_/2)]);
    if (t0 >= 1) h2v = __half22float2(valh2[base - 1*(DI_/2)]);
    #pragma unroll
    for (int j = 0; j < 8; j++) {
        size_t idx = base + (size_t)j * (DI_/2);
        float2 cur = __half22float2(valh2[idx]);
        float vx = bias.x + wa.x*h0.x + wa.y*h1.x + wa.z*h2v.x + wa.w*cur.x;
        float vy = bias.y + wb.x*h0.y + wb.y*h1.y + wb.z*h2v.y + wb.w*cur.y;
        h0 = h1; h1 = h2v; h2v = cur;
        float sx = vx / (1.f + __expf(-vx));
        float sy = vy / (1.f + __expf(-vy));
        float2 gt = __half22float2(gateh2[idx]);
        hh2[idx] = __floats2half2_rn(sx * gt.x, sy * gt.y);
    }
}

// 32x32 tile transposes -------------------------------------------------------
__global__ void k_transV() {
    __shared__ __half sm[32][33];
    int b = blockIdx.z;
    int t0 = blockIdx.x * 32, d0 = blockIdx.y * 32;
    int tx = threadIdx.x & 31, ty = threadIdx.x >> 5;
    #pragma unroll
    for (int j = 0; j < 4; j++)
        sm[ty + j*8][tx] = g_vh[((size_t)b*T_ + t0 + ty + j*8)*D_ + d0 + tx];
    __syncthreads();
    float gw = __expf((float)(CB_ - 1 - ((t0 + tx) % CB_)) * g_consts[0]);
    #pragma unroll
    for (int j = 0; j < 4; j++) {
        size_t o = ((size_t)b*D_ + d0 + ty + j*8)*T_ + t0 + tx;
        __half v = sm[tx][ty + j*8];
        g_vT[o] = v;
        g_vTs[o] = __float2half(__half2float(v) * gw);
    }
}

__global__ void k_transK() {
    __shared__ __half sm[32][33];
    int b = blockIdx.z;
    int t0 = blockIdx.x * 32, d0 = blockIdx.y * 32;
    int tx = threadIdx.x & 31, ty = threadIdx.x >> 5;
    #pragma unroll
    for (int j = 0; j < 4; j++) {
        int t = t0 + ty + j*8;
        sm[ty + j*8][tx] = (t > 0)
            ? g_outh[((size_t)b*T_ + t - 1)*D_ + d0 + tx] : __float2half(0.f);
    }
    __syncthreads();
    #pragma unroll
    for (int j = 0; j < 4; j++)
        g_koutT[((size_t)b*D_ + d0 + ty + j*8)*T_ + t0 + tx] = sm[tx][ty + j*8];
}

// ---------------- dense fp16 TN GEMM -----------------------------------------
// mode 0: acc ; 1: silu ; 2: add1+add2+alpha*acc. C (fp32) / Ch (fp16) optional.
__global__ __launch_bounds__(256, 2) void k_hgemm16(
    const __half* __restrict__ A, const __half* __restrict__ Bm,
    float* __restrict__ C, __half* __restrict__ Ch, int N, int K,
    int mode, const float* __restrict__ add1, const float* __restrict__ add2)
{
    extern __shared__ __align__(16) __half sm16[];
    __half* As = sm16;
    __half* Bs = sm16 + NKST_ * STAGE_HALFS_;
    int tid = threadIdx.x;
    int m0 = blockIdx.y * 128, n0 = blockIdx.x * 128;
    int warp = tid >> 5, lane = tid & 31;
    int warp_m = warp >> 1, warp_n = warp & 1;
    int g = lane >> 2, tq = lane & 3;
    int lrow = tid >> 1, lc = (tid & 1) * 2;
    float acc[2][8][4] = {};

    hloop(A + (size_t)(m0 + lrow) * K + lc * 8,
          Bm + (size_t)(n0 + lrow) * K + lc * 8,
          K >> 5, 16, As, Bs, acc, warp_m, warp_n, lane, tid);

    float alpha = (mode == 2) ? g_consts[1] : 0.f;
    #pragma unroll
    for (int mt = 0; mt < 2; mt++)
        #pragma unroll
        for (int h = 0; h < 2; h++) {
            int mi = m0 + warp_m * 32 + mt * 16 + g + h * 8;
            size_t row = (size_t)mi * N;
            #pragma unroll
            for (int nt = 0; nt < 8; nt++) {
                int ni = n0 + warp_n * 64 + nt * 8 + tq * 2;
                float c0 = acc[mt][nt][h*2 + 0];
                float c1 = acc[mt][nt][h*2 + 1];
                if (mode == 1) {
                    c0 = c0 / (1.f + __expf(-c0));
                    c1 = c1 / (1.f + __expf(-c1));
                } else if (mode == 2) {
                    float2 a1 = *(const float2*)(add1 + row + ni);
                    float2 a2 = *(const float2*)(add2 + row + ni);
                    c0 = a1.x + a2.x + alpha * c0;
                    c1 = a1.y + a2.y + alpha * c1;
                }
                if (C)  *(float2*)(C + row + ni) = make_float2(c0, c1);
                if (Ch) *(__half2*)(Ch + row + ni) = __floats2half2_rn(c0, c1);
            }
        }
}

// ---------------- batched pchunk: P = mask(r@k^T) -> fp16 -------------------
// Only 3 of 4 128x128 tiles are launched: (0,0),(128,0),(128,128).
// The (0,128) tile is identically zero and is never read by k_readsall.
__global__ __launch_bounds__(256, 2) void k_pchunk() {
    extern __shared__ __align__(16) __half sm16[];
    __half* As = sm16;
    __half* Bs = sm16 + NKST_ * STAGE_HALFS_;
    __shared__ float gpow[256];
    int zb = blockIdx.z; int s = zb >> 3; int b = zb & 7;
    int t0 = s * CB_;
    int ti = blockIdx.x;                       // 0,1,2
    int m0 = (ti == 0) ? 0 : 128;
    int n0 = (ti == 2) ? 128 : 0;
    int tid = threadIdx.x;
    int warp = tid >> 5, lane = tid & 31;
    int warp_m = warp >> 1, warp_n = warp & 1;
    int g = lane >> 2, tq = lane & 3;
    int lrow = tid >> 1, lc = (tid & 1) * 2;
    float acc[2][8][4] = {};
    gpow[tid] = __expf((float)tid * g_consts[0]);

    int tok = t0 + n0 + lrow - 1;
    int bsz = (tok >= 0) ? 16 : 0;
    int tokc = (tok >= 0) ? tok : 0;
    hloop(g_outh + ((size_t)b*T_ + t0 + m0 + lrow)*D_ + lc*8,
          g_outh + ((size_t)b*T_ + tokc)*D_ + lc*8,
          D_ >> 5, bsz, As, Bs, acc, warp_m, warp_n, lane, tid);

    __half* P = g_Ph + (size_t)(s * B_ + b) * CB_ * CB_;
    #pragma unroll
    for (int mt = 0; mt < 2; mt++)
        #pragma unroll
        for (int h = 0; h < 2; h++) {
            int ii = m0 + warp_m * 32 + mt * 16 + g + h * 8;
            #pragma unroll
            for (int nt = 0; nt < 8; nt++) {
                int jj = n0 + warp_n * 64 + nt * 8 + tq * 2;
                float c0 = (ii > jj)     ? acc[mt][nt][h*2+0] * gpow[ii-1-jj] : 0.f;
                float c1 = (ii > jj + 1) ? acc[mt][nt][h*2+1] * gpow[ii-2-jj] : 0.f;
                *(__half2*)(P + (size_t)ii * CB_ + jj) = __floats2half2_rn(c0, c1);
            }
        }
}

// ---------------- batched U: U_s = vTs_s @ koutT_s^T ------------------------
__global__ __launch_bounds__(256, 2) void k_updateU() {
    extern __shared__ __align__(16) __half sm16[];
    __half* As = sm16;
    __half* Bs = sm16 + NKST_ * STAGE_HALFS_;
    int zb = blockIdx.z; int s = zb >> 3; int b = zb & 7;
    int t0 = s * CB_;
    int tid = threadIdx.x;
    int m0 = blockIdx.y * 128, n0 = blockIdx.x * 128;
    int warp = tid >> 5, lane = tid & 31;
    int warp_m = warp >> 1, warp_n = warp & 1;
    int g = lane >> 2, tq = lane & 3;
    int lrow = tid >> 1, lc = (tid & 1) * 2;
    float acc[2][8][4] = {};

    hloop(g_vTs + ((size_t)b*D_ + m0 + lrow)*T_ + t0 + lc*8,
          g_koutT + ((size_t)b*D_ + n0 + lrow)*T_ + t0 + lc*8,
          CB_ >> 5, 16, As, Bs, acc, warp_m, warp_n, lane, tid);

    __half* U = g_U + (size_t)(s * B_ + b) * DD_;
    #pragma unroll
    for (int mt = 0; mt < 2; mt++)
        #pragma unroll
        for (int h = 0; h < 2; h++) {
            int d = m0 + warp_m * 32 + mt * 16 + g + h * 8;
            #pragma unroll
            for (int nt = 0; nt < 8; nt++) {
                int e = n0 + warp_n * 64 + nt * 8 + tq * 2;
                *(__half2*)(U + (size_t)d * D_ + e) =
                    __floats2half2_rn(acc[mt][nt][h*2+0], acc[mt][nt][h*2+1]);
            }
        }
}

// ---------------- W prefix scan: Whs[s] = sum_{j<s} gC^{s-1-j} U_j ----------
__global__ void k_wscan() {
    int b = blockIdx.y;
    size_t off0 = (size_t)b * DD_ + (size_t)blockIdx.x * 8192;
    int tid = threadIdx.x;
    float gC = __expf((float)CB_ * g_consts[0]);
    float W[32] = {};
    for (int s = 0; s < NSTEP_; s++) {
        size_t so = (size_t)(s * B_) * DD_ + off0;
        #pragma unroll
        for (int k = 0; k < 4; k++) {
            size_t o = so + (size_t)k * 2048 + tid * 8;
            __half2 h0 = __floats2half2_rn(W[k*8+0], W[k*8+1]);
            __half2 h1 = __floats2half2_rn(W[k*8+2], W[k*8+3]);
            __half2 h2 = __floats2half2_rn(W[k*8+4], W[k*8+5]);
            __half2 h3 = __floats2half2_rn(W[k*8+6], W[k*8+7]);
            uint4 pack;
            pack.x = *(uint32_t*)&h0; pack.y = *(uint32_t*)&h1;
            pack.z = *(uint32_t*)&h2; pack.w = *(uint32_t*)&h3;
            *(uint4*)(g_Whs + o) = pack;
            uint4 u = *(const uint4*)(g_U + o);
            __half2 u0 = *(__half2*)&u.x, u1 = *(__half2*)&u.y;
            __half2 u2 = *(__half2*)&u.z, u3 = *(__half2*)&u.w;
            float2 f0 = __half22float2(u0), f1 = __half22float2(u1);
            float2 f2 = __half22float2(u2), f3 = __half22float2(u3);
            W[k*8+0] = gC*W[k*8+0] + f0.x; W[k*8+1] = gC*W[k*8+1] + f0.y;
            W[k*8+2] = gC*W[k*8+2] + f1.x; W[k*8+3] = gC*W[k*8+3] + f1.y;
            W[k*8+4] = gC*W[k*8+4] + f2.x; W[k*8+5] = gC*W[k*8+5] + f2.y;
            W[k*8+6] = gC*W[k*8+6] + f3.x; W[k*8+7] = gC*W[k*8+7] + f3.y;
        }
    }
}

// ---------------- batched reads: inter + intra fused ------------------------
// reads[t0+i, d] = gamma^i * sum_e out[t0+i,e] Whs[s][d,e]  +  sum_j P[i,j] vT[d,j]
// For m0=0 tiles, P rows only have nonzero j < 128 -> contract half the range.
__global__ __launch_bounds__(256, 2) void k_readsall() {
    extern __shared__ __align__(16) __half sm16[];
    __half* As = sm16;
    __half* Bs = sm16 + NKST_ * STAGE_HALFS_;
    int zb = blockIdx.z; int s = zb >> 3; int b = zb & 7;
    int t0 = s * CB_;
    int tid = threadIdx.x;
    int m0 = blockIdx.y * 128, n0 = blockIdx.x * 128;   // m over CB, n over D
    int warp = tid >> 5, lane = tid & 31;
    int warp_m = warp >> 1, warp_n = warp & 1;
    int g = lane >> 2, tq = lane & 3;
    int lrow = tid >> 1, lc = (tid & 1) * 2;
    float lg = g_consts[0];
    float acc[2][8][4] = {};

    // phase 1: inter = out @ Whs[s]^T
    hloop(g_outh + ((size_t)b*T_ + t0 + m0 + lrow)*D_ + lc*8,
          g_Whs + (size_t)(s * B_ + b) * DD_ + (size_t)(n0 + lrow)*D_ + lc*8,
          D_ >> 5, 16, As, Bs, acc, warp_m, warp_n, lane, tid);

    // scale by gamma^i
    #pragma unroll
    for (int mt = 0; mt < 2; mt++)
        #pragma unroll
        for (int h = 0; h < 2; h++) {
            int mi = m0 + warp_m * 32 + mt * 16 + g + h * 8;
            float sc = __expf((float)mi * lg);
            #pragma unroll
            for (int nt = 0; nt < 8; nt++) {
                acc[mt][nt][h*2+0] *= sc;
                acc[mt][nt][h*2+1] *= sc;
            }
        }

    // phase 2: intra = P @ vT^T  (m0=0: only j<128 can be nonzero)
    int nk2 = (m0 == 0) ? (128 >> 5) : (CB_ >> 5);
    hloop(g_Ph + (size_t)(s * B_ + b) * CB_ * CB_ + (size_t)(m0 + lrow) * CB_ + lc*8,
          g_vT + ((size_t)b*D_ + n0 + lrow)*T_ + t0 + lc*8,
          nk2, 16, As, Bs, acc, warp_m, warp_n, lane, tid);

    #pragma unroll
    for (int mt = 0; mt < 2; mt++)
        #pragma unroll
        for (int h = 0; h < 2; h++) {
            int mi = m0 + warp_m * 32 + mt * 16 + g + h * 8;
            size_t row = ((size_t)b * T_ + t0 + mi) * D_;
            #pragma unroll
            for (int nt = 0; nt < 8; nt++) {
                int ni = n0 + warp_n * 64 + nt * 8 + tq * 2;
                *(__half2*)(g_readsh + row + ni) =
                    __floats2half2_rn(acc[mt][nt][h*2+0], acc[mt][nt][h*2+1]);
            }
        }
}

// ---------------- launch ----------------------------------------------------
extern "C" void kernel_launch(void* const* d_in, const int* in_sizes, int n_in,
                              void* d_out, int out_size) {
    const float* x         = (const float*)d_in[0];
    const float* norm_w    = (const float*)d_in[1];
    const float* proj_w    = (const float*)d_in[2];
    const float* gate_w    = (const float*)d_in[3];
    const float* conv_w    = (const float*)d_in[4];
    const float* conv_b    = (const float*)d_in[5];
    const float* out_proj  = (const float*)d_in[6];
    const float* write_w   = (const float*)d_in[7];
    const float* read_w    = (const float*)d_in[8];
    const float* decay     = (const float*)d_in[9];
    const float* log_alpha = (const float*)d_in[10];
    float* out = (float*)d_out;

    float* p_out;
    __half *p_xnh, *p_valh, *p_gateh, *p_hh, *p_outh, *p_vh, *p_readsh, *p_wh;
    cudaGetSymbolAddress((void**)&p_out,    g_out);
    cudaGetSymbolAddress((void**)&p_xnh,    g_xnh);
    cudaGetSymbolAddress((void**)&p_valh,   g_valh);
    cudaGetSymbolAddress((void**)&p_gateh,  g_gateh);
    cudaGetSymbolAddress((void**)&p_hh,     g_hh);
    cudaGetSymbolAddress((void**)&p_outh,   g_outh);
    cudaGetSymbolAddress((void**)&p_vh,     g_vh);
    cudaGetSymbolAddress((void**)&p_readsh, g_readsh);
    cudaGetSymbolAddress((void**)&p_wh,     g_wh);
    __half* wh_proj  = p_wh;
    __half* wh_gate  = p_wh + 1179648;
    __half* wh_outp  = p_wh + 2359296;
    __half* wh_write = p_wh + 3538944;
    __half* wh_read  = p_wh + 4128768;

    static int smem_set = 0;
    if (!smem_set) {
        cudaFuncSetAttribute(k_hgemm16, cudaFuncAttributeMaxDynamicSharedMemorySize, GSM_);
        cudaFuncSetAttribute(k_pchunk,  cudaFuncAttributeMaxDynamicSharedMemorySize, GSM_);
        cudaFuncSetAttribute(k_updateU, cudaFuncAttributeMaxDynamicSharedMemorySize, GSM_);
        cudaFuncSetAttribute(k_readsall,cudaFuncAttributeMaxDynamicSharedMemorySize, GSM_);
        smem_set = 1;
    }

    k_consts<<<1, 1>>>(decay, log_alpha);
    k_h2all<<<2359296/256, 256>>>(proj_w, gate_w, out_proj, write_w, read_w);
    k_xnorm<<<M_/8, 256>>>(x, norm_w);

    // val(fp16) = xn @ proj^T ; gate(fp16) = silu(xn @ gate^T)
    k_hgemm16<<<dim3(DI_/128, M_/128), 256, GSM_>>>(
        p_xnh, wh_proj, nullptr, p_valh, DI_, D_, 0, nullptr, nullptr);
    k_hgemm16<<<dim3(DI_/128, M_/128), 256, GSM_>>>(
        p_xnh, wh_gate, nullptr, p_gateh, DI_, D_, 1, nullptr, nullptr);
    // h(fp16) = silu(conv(val)+b) * gate
    k_conv<<<dim3(DI_/512, T_/8, B_), 256>>>(conv_w, conv_b);
    // out = h @ out_proj^T  (fp32 + fp16)
    k_hgemm16<<<dim3(D_/128, M_/128), 256, GSM_>>>(
        p_hh, wh_outp, p_out, p_outh, D_, DI_, 0, nullptr, nullptr);
    // v(fp16) = out @ write^T
    k_hgemm16<<<dim3(D_/128, M_/128), 256, GSM_>>>(
        p_outh, wh_write, nullptr, p_vh, D_, D_, 0, nullptr, nullptr);

    // transposed fp16 operand copies
    k_transV<<<dim3(T_/32, D_/32, B_), 256>>>();
    k_transK<<<dim3(T_/32, D_/32, B_), 256>>>();

    // fully-parallel chunk work (pchunk: 3 non-zero tiles only)
    k_pchunk <<<dim3(3, 1, NSTEP_*B_), 256, GSM_>>>();
    k_updateU<<<dim3(D_/128,  D_/128,  NSTEP_*B_), 256, GSM_>>>();

    // prefix scan of W snapshots
    k_wscan<<<dim3((int)(DD_/8192), B_), 256>>>();

    // fused inter+intra reads (one wide launch)
    k_readsall<<<dim3(D_/128, CB_/128, NSTEP_*B_), 256, GSM_>>>();

    // final: y = x + out + alpha * (reads @ read^T)
    k_hgemm16<<<dim3(D_/128, M_/128), 256, GSM_>>>(
        p_readsh, wh_read, out, nullptr, D_, D_, 2, x, p_out);
}